// round 9
// baseline (speedup 1.0000x reference)
#include <cuda_runtime.h>
#include <cuda_fp16.h>
#include <cstdint>

typedef unsigned long long ull;

// Problem shape (fixed by the dataset)
#define NN 50000     // nodes
#define KK 256       // in feats
#define MM 128       // out feats
#define EE 800000    // edges

// Static scratch (no allocs allowed). Zero-initialized at load; reduce_kernel
// restores g_cnt to zero each launch, so the hist invariant holds every call.
__device__ __half g_hw[(size_t)NN * MM];  // h @ W in fp16 (12.8 MB, L2-resident)
__device__ int   g_cnt[NN];               // degree histogram (zero at entry)
__device__ int   g_off[NN];               // CSR exclusive offsets
__device__ int   g_pos[NN];               // fill cursors
__device__ int   g_srcs[EE];              // src ids grouped by dst
// Lane-ordered tf32 B-fragment table (built by prep_kernel blocks 0..63):
//   g_wfrag[kg*512 + nt*32 + le] = ( tf32 W[kg*8 + (le&3)][nt*8 + (le>>2)],
//                                    tf32 W[kg*8 + (le&3) + 4][nt*8 + (le>>2)] )
__device__ float4 g_wfrag4[32 * 512 / 2];        // 128 KB

__device__ __forceinline__ unsigned f2tf32(float x) {
    unsigned r;
    asm("cvt.rna.tf32.f32 %0, %1;" : "=r"(r) : "f"(x));
    return r;
}

// ---------------------------------------------------------------------------
// K0: prep — blocks 0..63 build W-fragment table; blocks 64.. histogram dst.
// ---------------------------------------------------------------------------
#define WFRAG_BLOCKS 64
__global__ __launch_bounds__(256)
void prep_kernel(const float* __restrict__ W, const int* __restrict__ dst, int E) {
    if (blockIdx.x < WFRAG_BLOCKS) {
        const int idx = blockIdx.x * 256 + threadIdx.x;   // 0 .. 16383
        const int kg = idx >> 9;          // k-step group 0..31
        const int r  = idx & 511;
        const int nt = r >> 5;            // 0..15
        const int le = r & 31;
        const int lq  = le & 3;
        const int ll4 = le >> 2;
        const int col = nt * 8 + ll4;
        const int k0  = kg * 8 + lq;
        float2* out = (float2*)g_wfrag4;
        out[idx] = make_float2(
            __uint_as_float(f2tf32(W[k0 * MM + col])),
            __uint_as_float(f2tf32(W[(k0 + 4) * MM + col])));
    } else {
        const int e = (blockIdx.x - WFRAG_BLOCKS) * 256 + threadIdx.x;
        if (e < E) atomicAdd(&g_cnt[dst[e]], 1);
    }
}

// ---------------------------------------------------------------------------
// K1: block 0 = full exclusive scan of g_cnt -> g_off,g_pos (hidden under GEMM)
//     blocks 1..782 = hw = h @ W via mma.sync m16n8k8 tf32.
//
// GEMM CTA: 64 rows x 128 cols, 128 threads = 4 warps x 16 rows.
// smem 50176 B -> 4 CTAs/SM; 64 accum regs/thread.
//   hs[64][68]  tf32-bit h chunk; A-frag banks = 4*l4 + q -> conflict-free
//   Wk[8][512]  per-chunk B fragments, copied coalesced from g_wfrag4
// ---------------------------------------------------------------------------
#define HS_PAD 68
#define HS_FLOATS (64 * HS_PAD)                     // 4352 floats = 17408 B
#define GEMM_SMEM (HS_FLOATS * 4 + 8 * 512 * 8)     // 17408 + 32768 = 50176 B
#define SCAN_TILES ((NN + 511) / 512)               // 98

__device__ void scan_block_50k() {
    // 128 threads: sequential 512-tiles; 4 consecutive elems/thread/tile.
    __shared__ int warp_tot[4];
    const int tid  = threadIdx.x;
    const int lane = tid & 31;
    const int warp = tid >> 5;
    int running = 0;

    for (int tile = 0; tile < SCAN_TILES; tile++) {
        const int base = tile * 512 + tid * 4;
        int v0 = (base     < NN) ? g_cnt[base]     : 0;
        int v1 = (base + 1 < NN) ? g_cnt[base + 1] : 0;
        int v2 = (base + 2 < NN) ? g_cnt[base + 2] : 0;
        int v3 = (base + 3 < NN) ? g_cnt[base + 3] : 0;
        const int s0 = v0, s1 = s0 + v1, s2 = s1 + v2, s3 = s2 + v3;

        // warp inclusive scan of per-thread sums
        int x = s3;
        #pragma unroll
        for (int off = 1; off < 32; off <<= 1) {
            int y = __shfl_up_sync(0xffffffffu, x, off);
            if (lane >= off) x += y;
        }
        if (lane == 31) warp_tot[warp] = x;
        __syncthreads();
        int wb = 0;
        #pragma unroll
        for (int w = 0; w < 4; w++) if (w < warp) wb += warp_tot[w];
        const int tile_total = warp_tot[0] + warp_tot[1] + warp_tot[2] + warp_tot[3];
        const int bx = running + wb + (x - s3);   // exclusive base for this thread

        if (base     < NN) { g_off[base]     = bx;      g_pos[base]     = bx;      }
        if (base + 1 < NN) { g_off[base + 1] = bx + s0; g_pos[base + 1] = bx + s0; }
        if (base + 2 < NN) { g_off[base + 2] = bx + s1; g_pos[base + 2] = bx + s1; }
        if (base + 3 < NN) { g_off[base + 3] = bx + s2; g_pos[base + 3] = bx + s2; }

        running += tile_total;
        __syncthreads();   // protect warp_tot before next tile's writes
    }
}

__global__ __launch_bounds__(128, 4)
void gemm_scan_kernel(const float* __restrict__ h) {
    if (blockIdx.x == 0) { scan_block_50k(); return; }

    extern __shared__ float smem[];
    float*  hs  = smem;                          // [64][HS_PAD]
    float2* Wk  = (float2*)(smem + HS_FLOATS);   // [8][512]
    float4* Wk4 = (float4*)Wk;

    const int tid  = threadIdx.x;
    const int warp = tid >> 5;
    const int lane = tid & 31;
    const int q    = lane & 3;    // k-offset within frag
    const int l4   = lane >> 2;   // row/col group

    const int blk_row0 = (blockIdx.x - 1) * 64;

    float d[16][4];
    #pragma unroll
    for (int nt = 0; nt < 16; nt++)
        #pragma unroll
        for (int j = 0; j < 4; j++) d[nt][j] = 0.f;

    for (int kc = 0; kc < 4; kc++) {            // 4 chunks of K=64
        if (kc) __syncthreads();                // drain readers before restage

        // stage B fragments: coalesced float4 copy (2048 float4, 16/thread)
        {
            const float4* src = g_wfrag4 + kc * (8 * 512 / 2);
            #pragma unroll
            for (int i = 0; i < 16; i++)
                Wk4[tid + i * 128] = __ldg(src + tid + i * 128);
        }
        // stage h chunk: 64 rows x 64 cols, tf32-converted (1024 float4, 8/thread)
        #pragma unroll
        for (int i = 0; i < 8; i++) {
            const int e   = tid + i * 128;      // 0..1023
            const int row = e >> 4;
            const int f4  = e & 15;
            int rg = blk_row0 + row;
            if (rg >= NN) rg = NN - 1;
            float4 v = __ldg((const float4*)(h + (size_t)rg * KK + kc * 64) + f4);
            v.x = __uint_as_float(f2tf32(v.x));
            v.y = __uint_as_float(f2tf32(v.y));
            v.z = __uint_as_float(f2tf32(v.z));
            v.w = __uint_as_float(f2tf32(v.w));
            ((float4*)(hs + row * HS_PAD))[f4] = v;
        }
        __syncthreads();

        #pragma unroll
        for (int ks = 0; ks < 8; ks++) {        // 8 k-steps of 8
            const int k8 = ks * 8;
            const int ar = warp * 16 + l4;
            const unsigned a0 = __float_as_uint(hs[(ar    ) * HS_PAD + k8 + q    ]);
            const unsigned a1 = __float_as_uint(hs[(ar + 8) * HS_PAD + k8 + q    ]);
            const unsigned a2 = __float_as_uint(hs[(ar    ) * HS_PAD + k8 + q + 4]);
            const unsigned a3 = __float_as_uint(hs[(ar + 8) * HS_PAD + k8 + q + 4]);
            const float2* wrow = Wk + ks * 512;

            #pragma unroll
            for (int nt = 0; nt < 16; nt++) {
                const float2 bb = wrow[nt * 32 + lane];   // coalesced LDS.64
                asm("mma.sync.aligned.m16n8k8.row.col.f32.tf32.tf32.f32 "
                    "{%0,%1,%2,%3}, {%4,%5,%6,%7}, {%8,%9}, {%0,%1,%2,%3};"
                    : "+f"(d[nt][0]), "+f"(d[nt][1]),
                      "+f"(d[nt][2]), "+f"(d[nt][3])
                    : "r"(a0), "r"(a1), "r"(a2), "r"(a3),
                      "r"(__float_as_uint(bb.x)), "r"(__float_as_uint(bb.y)));
            }
        }
    }

    // epilogue: fp16 store. d0,d1 at (l4, 2q..2q+1), d2,d3 at (l4+8, ..)
    const int r0 = blk_row0 + warp * 16 + l4;
    #pragma unroll
    for (int nt = 0; nt < 16; nt++) {
        const int col = nt * 8 + q * 2;
        if (r0 < NN)
            *(__half2*)(g_hw + (size_t)r0 * MM + col) =
                __floats2half2_rn(d[nt][0], d[nt][1]);
        if (r0 + 8 < NN)
            *(__half2*)(g_hw + (size_t)(r0 + 8) * MM + col) =
                __floats2half2_rn(d[nt][2], d[nt][3]);
    }
}

// ---------------------------------------------------------------------------
// K2: fill — bucket src ids into CSR order
// ---------------------------------------------------------------------------
__global__ void fill_kernel(const int* __restrict__ src, const int* __restrict__ dst, int E) {
    int e = blockIdx.x * blockDim.x + threadIdx.x;
    if (e < E) {
        int p = atomicAdd(&g_pos[dst[e]], 1);
        g_srcs[p] = src[e];
    }
}

// ---------------------------------------------------------------------------
// K3: segmented reduce — one warp per node; fp16 gather, fp32 accumulate;
// fused bias + relu. Zeroes g_cnt[n] for the next launch.
// ---------------------------------------------------------------------------
__global__ __launch_bounds__(256)
void reduce_kernel(const float* __restrict__ b, float* __restrict__ out) {
    const int n = (int)((blockIdx.x * (unsigned)blockDim.x + threadIdx.x) >> 5);
    if (n >= NN) return;
    const int lane = threadIdx.x & 31;

    const int beg = g_off[n];
    const int deg = g_cnt[n];
    if (lane == 0) g_cnt[n] = 0;   // restore invariant for next launch

    float4 acc = make_float4(0.f, 0.f, 0.f, 0.f);

    int i = 0;
    for (; i + 4 <= deg; i += 4) {
        const int s0 = __ldg(&g_srcs[beg + i]);
        const int s1 = __ldg(&g_srcs[beg + i + 1]);
        const int s2 = __ldg(&g_srcs[beg + i + 2]);
        const int s3 = __ldg(&g_srcs[beg + i + 3]);
        const uint2 v0 = __ldg((const uint2*)(g_hw + (size_t)s0 * MM) + lane);
        const uint2 v1 = __ldg((const uint2*)(g_hw + (size_t)s1 * MM) + lane);
        const uint2 v2 = __ldg((const uint2*)(g_hw + (size_t)s2 * MM) + lane);
        const uint2 v3 = __ldg((const uint2*)(g_hw + (size_t)s3 * MM) + lane);
        #pragma unroll
        for (int j = 0; j < 4; j++) {
            const uint2 vv = (j == 0) ? v0 : (j == 1) ? v1 : (j == 2) ? v2 : v3;
            const float2 p0 = __half22float2(*(const __half2*)&vv.x);
            const float2 p1 = __half22float2(*(const __half2*)&vv.y);
            acc.x += p0.x; acc.y += p0.y; acc.z += p1.x; acc.w += p1.y;
        }
    }
    for (; i < deg; i++) {
        const int s0 = __ldg(&g_srcs[beg + i]);
        const uint2 v0 = __ldg((const uint2*)(g_hw + (size_t)s0 * MM) + lane);
        const float2 p0 = __half22float2(*(const __half2*)&v0.x);
        const float2 p1 = __half22float2(*(const __half2*)&v0.y);
        acc.x += p0.x; acc.y += p0.y; acc.z += p1.x; acc.w += p1.y;
    }

    const float4 bv = __ldg((const float4*)b + lane);
    acc.x = fmaxf(acc.x + bv.x, 0.f);
    acc.y = fmaxf(acc.y + bv.y, 0.f);
    acc.z = fmaxf(acc.z + bv.z, 0.f);
    acc.w = fmaxf(acc.w + bv.w, 0.f);

    ((float4*)(out + (size_t)n * MM))[lane] = acc;
}

// ---------------------------------------------------------------------------
// Launch: h, W, b, src, dst  ->  out [N, 128] fp32   (4 kernels total)
// ---------------------------------------------------------------------------
extern "C" void kernel_launch(void* const* d_in, const int* in_sizes, int n_in,
                              void* d_out, int out_size) {
    const float* h = (const float*)d_in[0];
    const float* W = (const float*)d_in[1];
    const float* b = (const float*)d_in[2];
    const int* src = (const int*)d_in[3];
    const int* dst = (const int*)d_in[4];
    float* out = (float*)d_out;

    const int E = in_sizes[3];

    static bool attr_set = false;
    if (!attr_set) {
        cudaFuncSetAttribute(gemm_scan_kernel,
                             cudaFuncAttributeMaxDynamicSharedMemorySize,
                             GEMM_SMEM);
        attr_set = true;
    }

    // K0: wfrag table + dst histogram (independent, one grid)
    {
        const int hist_blocks = (E + 255) / 256;
        prep_kernel<<<WFRAG_BLOCKS + hist_blocks, 256>>>(W, dst, E);
    }
    // K1: GEMM (blocks 1..) + full CSR scan (block 0, hidden under GEMM)
    gemm_scan_kernel<<<1 + (NN + 63) / 64, 128, GEMM_SMEM>>>(h);

    // K2: CSR fill
    fill_kernel<<<(E + 255) / 256, 256>>>(src, dst, E);

    // K3: segmented reduce + bias + relu (one warp per node)
    {
        const long long threads = (long long)NN * 32;
        reduce_kernel<<<(int)((threads + 255) / 256), 256>>>(b, out);
    }
}

// round 10
// speedup vs baseline: 1.2974x; 1.2974x over previous
#include <cuda_runtime.h>
#include <cuda_fp16.h>
#include <cstdint>

typedef unsigned long long ull;

// Problem shape (fixed by the dataset)
#define NN 50000     // nodes
#define KK 256       // in feats
#define MM 128       // out feats
#define EE 800000    // edges

// Static scratch (no allocs allowed). Zero-initialized at load; reduce_kernel
// restores g_cnt to zero each launch, so the hist invariant holds every call.
__device__ __half g_hw[(size_t)NN * MM];  // h @ W in fp16 (12.8 MB, L2-resident)
__device__ int   g_cnt[NN];               // degree histogram (zero at entry)
__device__ int   g_off[NN];               // CSR exclusive offsets
__device__ int   g_pos[NN];               // fill cursors
__device__ int   g_srcs[EE];              // src ids grouped by dst
// Lane-ordered tf32 B-fragment table (built by prep_kernel blocks 0..63):
//   g_wfrag[kg*512 + nt*32 + le] = ( tf32 W[kg*8 + (le&3)][nt*8 + (le>>2)],
//                                    tf32 W[kg*8 + (le&3) + 4][nt*8 + (le>>2)] )
__device__ float4 g_wfrag4[32 * 512 / 2];        // 128 KB

__device__ __forceinline__ unsigned f2tf32(float x) {
    unsigned r;
    asm("cvt.rna.tf32.f32 %0, %1;" : "=r"(r) : "f"(x));
    return r;
}

// ---------------------------------------------------------------------------
// K0: prep — blocks 0..63 build W-fragment table; blocks 64.. histogram dst.
// ---------------------------------------------------------------------------
#define WFRAG_BLOCKS 64
__global__ __launch_bounds__(256)
void prep_kernel(const float* __restrict__ W, const int* __restrict__ dst, int E) {
    if (blockIdx.x < WFRAG_BLOCKS) {
        const int idx = blockIdx.x * 256 + threadIdx.x;   // 0 .. 16383
        const int kg = idx >> 9;          // k-step group 0..31
        const int r  = idx & 511;
        const int nt = r >> 5;            // 0..15
        const int le = r & 31;
        const int lq  = le & 3;
        const int ll4 = le >> 2;
        const int col = nt * 8 + ll4;
        const int k0  = kg * 8 + lq;
        float2* out = (float2*)g_wfrag4;
        out[idx] = make_float2(
            __uint_as_float(f2tf32(W[k0 * MM + col])),
            __uint_as_float(f2tf32(W[(k0 + 4) * MM + col])));
    } else {
        const int e = (blockIdx.x - WFRAG_BLOCKS) * 256 + threadIdx.x;
        if (e < E) atomicAdd(&g_cnt[dst[e]], 1);
    }
}

// ---------------------------------------------------------------------------
// K1: block 0 = full exclusive scan of g_cnt -> g_off,g_pos (prefetch-pipelined,
//     hidden under GEMM); blocks 1..782 = hw = h @ W via mma.sync m16n8k8 tf32.
// ---------------------------------------------------------------------------
#define HS_PAD 68
#define HS_FLOATS (64 * HS_PAD)                     // 4352 floats = 17408 B
#define GEMM_SMEM (HS_FLOATS * 4 + 8 * 512 * 8)     // 17408 + 32768 = 50176 B
#define SCAN_TILES ((NN + 511) / 512)               // 98
#define SCAN_PF 8

__device__ __forceinline__ int4 scan_load_tile(int t, int tid) {
    const int base = t * 512 + tid * 4;
    if (base + 3 < NN) return *(const int4*)&g_cnt[base];
    int4 v;
    v.x = (base     < NN) ? g_cnt[base]     : 0;
    v.y = (base + 1 < NN) ? g_cnt[base + 1] : 0;
    v.z = (base + 2 < NN) ? g_cnt[base + 2] : 0;
    v.w = (base + 3 < NN) ? g_cnt[base + 3] : 0;
    return v;
}

__device__ void scan_block_50k() {
    // 128 threads; 512-elem tiles; depth-8 register prefetch ring.
    __shared__ int warp_tot[4];
    const int tid  = threadIdx.x;
    const int lane = tid & 31;
    const int warp = tid >> 5;
    int running = 0;

    int4 buf[SCAN_PF];
    #pragma unroll
    for (int t = 0; t < SCAN_PF; t++) buf[t] = scan_load_tile(t, tid);

    for (int tb = 0; tb < SCAN_TILES; tb += SCAN_PF) {
        #pragma unroll
        for (int j = 0; j < SCAN_PF; j++) {
            const int tile = tb + j;
            if (tile >= SCAN_TILES) break;
            const int4 v = buf[j];
            // refill this slot for the next group (independent load, in flight
            // for the next ~SCAN_PF tile-steps)
            if (tile + SCAN_PF < SCAN_TILES)
                buf[j] = scan_load_tile(tile + SCAN_PF, tid);

            const int s0 = v.x, s1 = s0 + v.y, s2 = s1 + v.z, s3 = s2 + v.w;
            int x = s3;
            #pragma unroll
            for (int off = 1; off < 32; off <<= 1) {
                int y = __shfl_up_sync(0xffffffffu, x, off);
                if (lane >= off) x += y;
            }
            if (lane == 31) warp_tot[warp] = x;
            __syncthreads();
            int wb = 0;
            #pragma unroll
            for (int w = 0; w < 4; w++) if (w < warp) wb += warp_tot[w];
            const int tile_total = warp_tot[0] + warp_tot[1] + warp_tot[2] + warp_tot[3];
            const int bx = running + wb + (x - s3);

            const int base = tile * 512 + tid * 4;
            if (base     < NN) { g_off[base]     = bx;      g_pos[base]     = bx;      }
            if (base + 1 < NN) { g_off[base + 1] = bx + s0; g_pos[base + 1] = bx + s0; }
            if (base + 2 < NN) { g_off[base + 2] = bx + s1; g_pos[base + 2] = bx + s1; }
            if (base + 3 < NN) { g_off[base + 3] = bx + s2; g_pos[base + 3] = bx + s2; }

            running += tile_total;
            __syncthreads();
        }
    }
}

__global__ __launch_bounds__(128, 4)
void gemm_scan_kernel(const float* __restrict__ h) {
    if (blockIdx.x == 0) { scan_block_50k(); return; }

    extern __shared__ float smem[];
    float*  hs  = smem;                          // [64][HS_PAD]
    float2* Wk  = (float2*)(smem + HS_FLOATS);   // [8][512]
    float4* Wk4 = (float4*)Wk;

    const int tid  = threadIdx.x;
    const int warp = tid >> 5;
    const int lane = tid & 31;
    const int q    = lane & 3;    // k-offset within frag
    const int l4   = lane >> 2;   // row/col group

    const int blk_row0 = (blockIdx.x - 1) * 64;

    float d[16][4];
    #pragma unroll
    for (int nt = 0; nt < 16; nt++)
        #pragma unroll
        for (int j = 0; j < 4; j++) d[nt][j] = 0.f;

    for (int kc = 0; kc < 4; kc++) {            // 4 chunks of K=64
        if (kc) __syncthreads();                // drain readers before restage

        // stage B fragments: coalesced float4 copy (2048 float4, 16/thread)
        {
            const float4* src = g_wfrag4 + kc * (8 * 512 / 2);
            #pragma unroll
            for (int i = 0; i < 16; i++)
                Wk4[tid + i * 128] = __ldg(src + tid + i * 128);
        }
        // stage h chunk: 64 rows x 64 cols, tf32-converted (1024 float4, 8/thread)
        #pragma unroll
        for (int i = 0; i < 8; i++) {
            const int e   = tid + i * 128;      // 0..1023
            const int row = e >> 4;
            const int f4  = e & 15;
            int rg = blk_row0 + row;
            if (rg >= NN) rg = NN - 1;
            float4 v = __ldg((const float4*)(h + (size_t)rg * KK + kc * 64) + f4);
            v.x = __uint_as_float(f2tf32(v.x));
            v.y = __uint_as_float(f2tf32(v.y));
            v.z = __uint_as_float(f2tf32(v.z));
            v.w = __uint_as_float(f2tf32(v.w));
            ((float4*)(hs + row * HS_PAD))[f4] = v;
        }
        __syncthreads();

        #pragma unroll
        for (int ks = 0; ks < 8; ks++) {        // 8 k-steps of 8
            const int k8 = ks * 8;
            const int ar = warp * 16 + l4;
            const unsigned a0 = __float_as_uint(hs[(ar    ) * HS_PAD + k8 + q    ]);
            const unsigned a1 = __float_as_uint(hs[(ar + 8) * HS_PAD + k8 + q    ]);
            const unsigned a2 = __float_as_uint(hs[(ar    ) * HS_PAD + k8 + q + 4]);
            const unsigned a3 = __float_as_uint(hs[(ar + 8) * HS_PAD + k8 + q + 4]);
            const float2* wrow = Wk + ks * 512;

            #pragma unroll
            for (int nt = 0; nt < 16; nt++) {
                const float2 bb = wrow[nt * 32 + lane];   // coalesced LDS.64
                asm("mma.sync.aligned.m16n8k8.row.col.f32.tf32.tf32.f32 "
                    "{%0,%1,%2,%3}, {%4,%5,%6,%7}, {%8,%9}, {%0,%1,%2,%3};"
                    : "+f"(d[nt][0]), "+f"(d[nt][1]),
                      "+f"(d[nt][2]), "+f"(d[nt][3])
                    : "r"(a0), "r"(a1), "r"(a2), "r"(a3),
                      "r"(__float_as_uint(bb.x)), "r"(__float_as_uint(bb.y)));
            }
        }
    }

    // epilogue: fp16 store. d0,d1 at (l4, 2q..2q+1), d2,d3 at (l4+8, ..)
    const int r0 = blk_row0 + warp * 16 + l4;
    #pragma unroll
    for (int nt = 0; nt < 16; nt++) {
        const int col = nt * 8 + q * 2;
        if (r0 < NN)
            *(__half2*)(g_hw + (size_t)r0 * MM + col) =
                __floats2half2_rn(d[nt][0], d[nt][1]);
        if (r0 + 8 < NN)
            *(__half2*)(g_hw + (size_t)(r0 + 8) * MM + col) =
                __floats2half2_rn(d[nt][2], d[nt][3]);
    }
}

// ---------------------------------------------------------------------------
// K2: fill — bucket src ids into CSR order
// ---------------------------------------------------------------------------
__global__ void fill_kernel(const int* __restrict__ src, const int* __restrict__ dst, int E) {
    int e = blockIdx.x * blockDim.x + threadIdx.x;
    if (e < E) {
        int p = atomicAdd(&g_pos[dst[e]], 1);
        g_srcs[p] = src[e];
    }
}

// ---------------------------------------------------------------------------
// K3: segmented reduce v2 — one warp per node.
//   * 32 edge ids fetched with ONE coalesced lane-load, distributed via shfl
//   * gathers issued in independent batches of 8 (8 LDG.64 in flight/warp)
//   * remainder = predicated 8-batch (clamped id, fmaf mask) — no serial tail
//   * fp16 gather, fp32 accumulate, fused bias+relu; re-zeroes g_cnt[n]
// ---------------------------------------------------------------------------
__global__ __launch_bounds__(256)
void reduce_kernel(const float* __restrict__ b, float* __restrict__ out) {
    const int n = (int)((blockIdx.x * (unsigned)blockDim.x + threadIdx.x) >> 5);
    if (n >= NN) return;
    const int lane = threadIdx.x & 31;

    const int beg = g_off[n];
    const int deg = g_cnt[n];
    if (lane == 0) g_cnt[n] = 0;   // restore invariant for next launch

    float4 acc = make_float4(0.f, 0.f, 0.f, 0.f);
    const uint2* __restrict__ hwp = (const uint2*)g_hw;   // 32 uint2 per row

    for (int base = 0; base < deg; base += 32) {
        const int m = min(deg - base, 32);
        int myid = 0;
        if (lane < m) myid = __ldg(&g_srcs[beg + base + lane]);

        int i = 0;
        for (; i + 8 <= m; i += 8) {
            uint2 v[8];
            #pragma unroll
            for (int j = 0; j < 8; j++) {
                const int s = __shfl_sync(0xffffffffu, myid, i + j);
                v[j] = __ldg(hwp + (size_t)s * 32 + lane);
            }
            #pragma unroll
            for (int j = 0; j < 8; j++) {
                const float2 p0 = __half22float2(*(const __half2*)&v[j].x);
                const float2 p1 = __half22float2(*(const __half2*)&v[j].y);
                acc.x += p0.x; acc.y += p0.y; acc.z += p1.x; acc.w += p1.y;
            }
        }
        if (i < m) {
            uint2 v[8];
            float w[8];
            #pragma unroll
            for (int j = 0; j < 8; j++) {
                const int idx = i + j;
                const int s = __shfl_sync(0xffffffffu, myid, (idx < m) ? idx : 0);
                w[j] = (idx < m) ? 1.f : 0.f;
                v[j] = __ldg(hwp + (size_t)s * 32 + lane);
            }
            #pragma unroll
            for (int j = 0; j < 8; j++) {
                const float2 p0 = __half22float2(*(const __half2*)&v[j].x);
                const float2 p1 = __half22float2(*(const __half2*)&v[j].y);
                acc.x = fmaf(w[j], p0.x, acc.x);
                acc.y = fmaf(w[j], p0.y, acc.y);
                acc.z = fmaf(w[j], p1.x, acc.z);
                acc.w = fmaf(w[j], p1.y, acc.w);
            }
        }
    }

    const float4 bv = __ldg((const float4*)b + lane);
    acc.x = fmaxf(acc.x + bv.x, 0.f);
    acc.y = fmaxf(acc.y + bv.y, 0.f);
    acc.z = fmaxf(acc.z + bv.z, 0.f);
    acc.w = fmaxf(acc.w + bv.w, 0.f);

    ((float4*)(out + (size_t)n * MM))[lane] = acc;
}

// ---------------------------------------------------------------------------
// Launch: h, W, b, src, dst  ->  out [N, 128] fp32   (4 kernels total)
// ---------------------------------------------------------------------------
extern "C" void kernel_launch(void* const* d_in, const int* in_sizes, int n_in,
                              void* d_out, int out_size) {
    const float* h = (const float*)d_in[0];
    const float* W = (const float*)d_in[1];
    const float* b = (const float*)d_in[2];
    const int* src = (const int*)d_in[3];
    const int* dst = (const int*)d_in[4];
    float* out = (float*)d_out;

    const int E = in_sizes[3];

    static bool attr_set = false;
    if (!attr_set) {
        cudaFuncSetAttribute(gemm_scan_kernel,
                             cudaFuncAttributeMaxDynamicSharedMemorySize,
                             GEMM_SMEM);
        attr_set = true;
    }

    // K0: wfrag table + dst histogram (independent, one grid)
    {
        const int hist_blocks = (E + 255) / 256;
        prep_kernel<<<WFRAG_BLOCKS + hist_blocks, 256>>>(W, dst, E);
    }
    // K1: GEMM (blocks 1..) + full CSR scan (block 0, prefetch-pipelined)
    gemm_scan_kernel<<<1 + (NN + 63) / 64, 128, GEMM_SMEM>>>(h);

    // K2: CSR fill
    fill_kernel<<<(E + 255) / 256, 256>>>(src, dst, E);

    // K3: segmented reduce + bias + relu (one warp per node)
    {
        const long long threads = (long long)NN * 32;
        reduce_kernel<<<(int)((threads + 255) / 256), 256>>>(b, out);
    }
}